// round 17
// baseline (speedup 1.0000x reference)
#include <cuda_runtime.h>

#define B_ 256
#define T_ 2048
#define S_ 32
#define N_ 19
#define UNF 6
#define CLS 10
#define EPSV 1e-8f

// scratch for per-step motor outputs: flat[b][t]  (MOTOR == 1)
__device__ float g_flat[B_ * T_];

__device__ __forceinline__ float tanhf_a(float x) {
    float y; asm("tanh.approx.f32 %0, %1;" : "=f"(y) : "f"(x)); return y;
}
__device__ __forceinline__ float rcpf(float x) {
    float y; asm("rcp.approx.ftz.f32 %0, %1;" : "=f"(y) : "f"(x)); return y;
}

// sigmoid(sg*(v-mu)) = 0.5 + 0.5*tanh(0.5*sg*v - 0.5*sg*mu); constant 0.5*w
// parts folded into per-lane accumulator inits (Kns/Kds/Knr/Kdr).
//
// One warp per batch, lane = post-neuron. Block = 64 = 2 warps = 2 batches on
// 2 SMSPs; grid 128 -> 1 block/SM. No barriers in the 2048-step loop.
// Sensory tanh for step t+1 is interleaved into the 6 unfolds of step t so the
// MUFU pipe stays fed while the recurrent chain stalls on shfl/rcp latency.
__global__ __launch_bounds__(64, 1)
void ltc_kernel(const float* __restrict__ x,
                const float* __restrict__ input_w, const float* __restrict__ input_b,
                const float* __restrict__ s_mu,   const float* __restrict__ s_sigma,
                const float* __restrict__ s_w,    const float* __restrict__ s_erev,
                const float* __restrict__ mu,     const float* __restrict__ sigma,
                const float* __restrict__ w,      const float* __restrict__ erev,
                const float* __restrict__ gleak,  const float* __restrict__ vleak,
                const float* __restrict__ cm,
                const float* __restrict__ out_w,  const float* __restrict__ out_b,
                const int*   __restrict__ s_mask, const int* __restrict__ mask)
{
    // sensory tables: [s][lane] float4 (0.5*sg, -0.5*sg*mu, 0.5*wE, 0.5*wD)
    __shared__ float4 cs[S_ * 32];

    const int tid  = threadIdx.x;
    const int warp = tid >> 5, lane = tid & 31;
    const int b    = blockIdx.x * 2 + warp;
    const int ln   = (lane < N_) ? lane : (N_ - 1);   // idle lanes mirror neuron 18

    for (int i = tid; i < S_ * 32; i += 64) {
        int s = i >> 5, l = i & 31;
        int n = (l < N_) ? l : (N_ - 1);
        int idx = s * N_ + n;
        float sg = s_sigma[idx];
        float wm = 0.5f * s_w[idx] * (float)s_mask[idx];
        cs[i] = make_float4(0.5f * sg, -0.5f * sg * s_mu[idx], wm * s_erev[idx], wm);
    }
    __syncthreads();

    // recurrent constants in registers (compile-time indexed)
    float ra[N_], rb[N_], rwe[N_], rwd[N_];
    float Knr = 0.f, Kdr = 0.f;
    #pragma unroll
    for (int j = 0; j < N_; ++j) {
        int idx = j * N_ + ln;
        float sg = sigma[idx];
        float wm = 0.5f * w[idx] * (float)mask[idx];
        ra[j]  = 0.5f * sg;
        rb[j]  = -0.5f * sg * mu[idx];
        rwe[j] = wm * erev[idx];
        rwd[j] = wm;
        Knr += rwe[j];
        Kdr += rwd[j];
    }
    float Kns = 0.f, Kds = 0.f;
    #pragma unroll
    for (int s = 0; s < S_; ++s) {
        float4 c = cs[s * 32 + lane];
        Kns += c.z;
        Kds += c.w;
    }

    const float gl  = gleak[ln];
    const float cmt = cm[ln] * (float)UNF;
    const float Pc  = gl * vleak[ln];
    const float D0  = cmt + gl + EPSV;
    const float ow = out_w[0], ob = out_b[0];
    const float iw = input_w[lane], ib = input_b[lane];   // lane = sensory channel

    const float* xb = x + (size_t)b * T_ * S_;

    // ---- prologue: sensory sums for t = 0 ----
    float inp0 = fmaf(xb[lane], iw, ib);
    float ns = Kns, ds = Kds;
    #pragma unroll
    for (int s = 0; s < S_; ++s) {
        float iv = __shfl_sync(0xffffffffu, inp0, s);
        float4 c = cs[s * 32 + lane];
        float tv = tanhf_a(fmaf(c.x, iv, c.y));
        ns = fmaf(c.z, tv, ns);
        ds = fmaf(c.w, tv, ds);
    }
    float inp_next = fmaf(xb[S_ + lane], iw, ib);         // mapped input for t=1
    float v = 0.f;

    // sensory slice boundaries per unfold: 6+6+5+5+5+5 = 32
    const int SB[UNF + 1] = {0, 6, 12, 17, 22, 27, 32};

    for (int t = 0; t < T_; ++t) {
        float ns_n = Kns, ds_n = Kds;                      // sensory accum for t+1
        const float inp_n = inp_next;
        // raw x prefetch for t+2 (overlaps the whole step)
        float xraw = 0.f;
        if (t + 2 < T_) xraw = xb[(size_t)(t + 2) * S_ + lane];

        #pragma unroll
        for (int u = 0; u < UNF; ++u) {
            float nu = ns + Knr, du = ds + Kdr;
            #pragma unroll
            for (int j = 0; j < N_; ++j) {
                float vj = __shfl_sync(0xffffffffu, v, j);
                float tv = tanhf_a(fmaf(ra[j], vj, rb[j]));
                nu = fmaf(rwe[j], tv, nu);
                du = fmaf(rwd[j], tv, du);
            }
            // interleave a slice of next-step sensory work (independent of v)
            #pragma unroll
            for (int s = SB[u]; s < SB[u + 1]; ++s) {
                float iv = __shfl_sync(0xffffffffu, inp_n, s);
                float4 c = cs[s * 32 + lane];
                float tv = tanhf_a(fmaf(c.x, iv, c.y));
                ns_n = fmaf(c.z, tv, ns_n);
                ds_n = fmaf(c.w, tv, ds_n);
            }
            v = (fmaf(cmt, v, Pc) + nu) * rcpf(D0 + du);
        }

        if (lane == 0)
            g_flat[(size_t)b * T_ + t] = fmaf(v, ow, ob);

        ns = ns_n; ds = ds_n;
        inp_next = fmaf(xraw, iw, ib);                     // mapped input for t+2
    }
}

// FC over time: out[b][c] = sum_t flat[b][t] * fc_w[c][t] + fc_b[c]
__global__ __launch_bounds__(256)
void fc_kernel(const float* __restrict__ fc_w, const float* __restrict__ fc_b,
               float* __restrict__ out)
{
    const int b = blockIdx.x, tid = threadIdx.x;
    float acc[CLS];
    #pragma unroll
    for (int c = 0; c < CLS; ++c) acc[c] = 0.f;

    const float* fb = g_flat + (size_t)b * T_;
    for (int t = tid; t < T_; t += 256) {
        float f = fb[t];
        #pragma unroll
        for (int c = 0; c < CLS; ++c)
            acc[c] = fmaf(f, fc_w[c * T_ + t], acc[c]);
    }
    #pragma unroll
    for (int c = 0; c < CLS; ++c)
        #pragma unroll
        for (int off = 16; off; off >>= 1)
            acc[c] += __shfl_down_sync(0xffffffffu, acc[c], off);

    __shared__ float red[CLS][8];
    const int wid = tid >> 5, lane = tid & 31;
    if (lane == 0) {
        #pragma unroll
        for (int c = 0; c < CLS; ++c) red[c][wid] = acc[c];
    }
    __syncthreads();
    if (tid < CLS) {
        float s = fc_b[tid];
        #pragma unroll
        for (int k = 0; k < 8; ++k) s += red[tid][k];
        out[b * CLS + tid] = s;
    }
}

extern "C" void kernel_launch(void* const* d_in, const int* in_sizes, int n_in,
                              void* d_out, int out_size)
{
    const float* x        = (const float*)d_in[0];
    const float* input_w  = (const float*)d_in[1];
    const float* input_b  = (const float*)d_in[2];
    const float* s_mu     = (const float*)d_in[3];
    const float* s_sigma  = (const float*)d_in[4];
    const float* s_w      = (const float*)d_in[5];
    const float* s_erev   = (const float*)d_in[6];
    const float* mu       = (const float*)d_in[7];
    const float* sigma    = (const float*)d_in[8];
    const float* w        = (const float*)d_in[9];
    const float* erev     = (const float*)d_in[10];
    const float* gleak    = (const float*)d_in[11];
    const float* vleak    = (const float*)d_in[12];
    const float* cm       = (const float*)d_in[13];
    const float* output_w = (const float*)d_in[14];
    const float* output_b = (const float*)d_in[15];
    const float* fc_w     = (const float*)d_in[16];
    const float* fc_b     = (const float*)d_in[17];
    const int*   s_mask   = (const int*)d_in[18];
    const int*   mask     = (const int*)d_in[19];
    float* out = (float*)d_out;

    ltc_kernel<<<B_ / 2, 64>>>(x, input_w, input_b, s_mu, s_sigma, s_w, s_erev,
                               mu, sigma, w, erev, gleak, vleak, cm,
                               output_w, output_b, s_mask, mask);
    fc_kernel<<<B_, 256>>>(fc_w, fc_b, out);
}